// round 2
// baseline (speedup 1.0000x reference)
#include <cuda_runtime.h>

#define D 128
#define NMAX 100000
#define EMAX 1600000

// ---------------- scratch (no allocations allowed) ----------------
__device__ float g_h1[(size_t)NMAX * D];   // layer-0 output
__device__ float g_h2[(size_t)NMAX * D];   // layer-1 output
__device__ float g_hn[(size_t)NMAX * D];   // per-layer neighbor mean
__device__ int   g_deg[NMAX];
__device__ int   g_off[NMAX + 1];
__device__ int   g_pos[NMAX];
__device__ int   g_csr[EMAX];
__device__ float g_inv[NMAX];

typedef unsigned long long ull;

__device__ __forceinline__ ull fma2(ull a, ull b, ull c) {
    ull d;
    asm("fma.rn.f32x2 %0, %1, %2, %3;" : "=l"(d) : "l"(a), "l"(b), "l"(c));
    return d;
}
__device__ __forceinline__ ull splat2(float x) {
    ull d;
    asm("mov.b64 %0, {%1, %1};" : "=l"(d) : "r"(__float_as_uint(x)));
    return d;
}

// ---------------- CSR build ----------------
__global__ void k_zero_deg(int n) {
    int i = blockIdx.x * blockDim.x + threadIdx.x;
    if (i < n) g_deg[i] = 0;
}

__global__ void k_count(const int* __restrict__ dst, int e) {
    int i = blockIdx.x * blockDim.x + threadIdx.x;
    if (i < e) atomicAdd(&g_deg[dst[i]], 1);
}

__device__ __forceinline__ int warp_incl_scan(int v, int lane) {
#pragma unroll
    for (int s = 1; s < 32; s <<= 1) {
        int t = __shfl_up_sync(0xffffffffu, v, s);
        if (lane >= s) v += t;
    }
    return v;
}

// single-block exclusive scan over degrees -> offsets, plus inv_deg
__global__ void k_scan(int n) {
    __shared__ int wsum[32];
    __shared__ int s_carry;
    int lane = threadIdx.x & 31;
    int wid  = threadIdx.x >> 5;
    if (threadIdx.x == 0) s_carry = 0;
    __syncthreads();
    for (int base = 0; base < n; base += 1024) {
        int i = base + (int)threadIdx.x;
        int d = (i < n) ? g_deg[i] : 0;
        int incl = warp_incl_scan(d, lane);
        if (lane == 31) wsum[wid] = incl;
        __syncthreads();
        if (wid == 0) {
            int w = wsum[lane];
            w = warp_incl_scan(w, lane);
            wsum[lane] = w;
        }
        __syncthreads();
        int block_incl = incl + (wid ? wsum[wid - 1] : 0);
        int carry = s_carry;
        if (i < n) {
            int excl = carry + block_incl - d;
            g_off[i] = excl;
            g_pos[i] = excl;
            g_inv[i] = 1.0f / fmaxf((float)d, 1.0f);
        }
        __syncthreads();
        if (threadIdx.x == 1023) s_carry = carry + block_incl;
        __syncthreads();
    }
    if (threadIdx.x == 0) g_off[n] = s_carry;
}

__global__ void k_fill(const int* __restrict__ src, const int* __restrict__ dst, int e) {
    int i = blockIdx.x * blockDim.x + threadIdx.x;
    if (i < e) {
        int p = atomicAdd(&g_pos[dst[i]], 1);
        g_csr[p] = src[i];
    }
}

// ---------------- neighbor mean (warp per node, float4 per lane) ----------------
// 2-edge unroll: doubles per-warp MLP on the L2-latency-bound gather chain.
__global__ void k_agg(const float* __restrict__ xin, int sel, int n) {
    const float* hin = (sel == 0) ? xin : ((sel == 1) ? g_h1 : g_h2);
    int w = (blockIdx.x * blockDim.x + threadIdx.x) >> 5;
    if (w >= n) return;
    int lane = threadIdx.x & 31;
    int beg = g_off[w], end = g_off[w + 1];
    const float4* h4 = (const float4*)hin;
    float4 acc0 = make_float4(0.f, 0.f, 0.f, 0.f);
    float4 acc1 = make_float4(0.f, 0.f, 0.f, 0.f);
    int ei = beg;
    for (; ei + 1 < end; ei += 2) {
        int u0 = __ldg(&g_csr[ei]);
        int u1 = __ldg(&g_csr[ei + 1]);
        float4 v0 = h4[(size_t)u0 * 32 + lane];
        float4 v1 = h4[(size_t)u1 * 32 + lane];
        acc0.x += v0.x; acc0.y += v0.y; acc0.z += v0.z; acc0.w += v0.w;
        acc1.x += v1.x; acc1.y += v1.y; acc1.z += v1.z; acc1.w += v1.w;
    }
    if (ei < end) {
        int u = __ldg(&g_csr[ei]);
        float4 v = h4[(size_t)u * 32 + lane];
        acc0.x += v.x; acc0.y += v.y; acc0.z += v.z; acc0.w += v.w;
    }
    float s = g_inv[w];
    float4 o;
    o.x = (acc0.x + acc1.x) * s;
    o.y = (acc0.y + acc1.y) * s;
    o.z = (acc0.z + acc1.z) * s;
    o.w = (acc0.w + acc1.w) * s;
    ((float4*)g_hn)[(size_t)w * 32 + lane] = o;
}

// ---------------- fused out = relu(hin@Ws + hn@Wn + bias) ----------------
// Tile: 128 rows x 128 cols per block, K = 256 (hin||hn), 256 threads,
// 8x8 microtile per thread, packed f32x2 FMAs.
__global__ __launch_bounds__(256) void k_gemm(
    const float* __restrict__ xin, float* __restrict__ dout,
    const float* __restrict__ Wsl, const float* __restrict__ Wnl,
    const float* __restrict__ bias, int sel, int n) {
    const float* A0 = (sel == 0) ? xin : ((sel == 1) ? g_h1 : g_h2);
    const float* A1 = g_hn;
    float* out = (sel == 0) ? g_h1 : ((sel == 1) ? g_h2 : dout);

    __shared__ float sA[16 * 128];   // sA[k][row]
    __shared__ float sB[16 * 128];   // sB[k][col]

    int t = threadIdx.x;
    int tx = t & 15;          // col group
    int ty = t >> 4;          // row group
    int blockRow = blockIdx.x * 128;

    ull acc[8][4];
#pragma unroll
    for (int r = 0; r < 8; r++)
#pragma unroll
        for (int c = 0; c < 4; c++) acc[r][c] = 0ull;

    int arow  = t >> 1;         // 0..127
    int akoff = (t & 1) * 8;    // 0 or 8
    int grow  = blockRow + arow;
    int bk    = t >> 4;         // 0..15
    int bn    = (t & 15) * 4;   // 0..60

    for (int kb = 0; kb < 16; kb++) {
        int ks = kb * 16;
        const float* Asrc; const float* Bsrc; int kbase;
        if (ks < 128) { Asrc = A0; Bsrc = Wsl; kbase = ks; }
        else          { Asrc = A1; Bsrc = Wnl; kbase = ks - 128; }

        // Front-batch all global loads (max MLP before the barrier).
        float4 av0 = make_float4(0.f, 0.f, 0.f, 0.f);
        float4 av1 = make_float4(0.f, 0.f, 0.f, 0.f);
        if (grow < n) {
            const float* ap = Asrc + (size_t)grow * 128 + kbase + akoff;
            av0 = *(const float4*)(ap);
            av1 = *(const float4*)(ap + 4);
        }
        float4 bv0 = __ldg((const float4*)(Bsrc + (kbase + bk) * 128 + bn));
        float4 bv1 = __ldg((const float4*)(Bsrc + (kbase + bk) * 128 + 64 + bn));

        __syncthreads();   // previous inner loop done reading smem
        sA[(akoff + 0) * 128 + arow] = av0.x;
        sA[(akoff + 1) * 128 + arow] = av0.y;
        sA[(akoff + 2) * 128 + arow] = av0.z;
        sA[(akoff + 3) * 128 + arow] = av0.w;
        sA[(akoff + 4) * 128 + arow] = av1.x;
        sA[(akoff + 5) * 128 + arow] = av1.y;
        sA[(akoff + 6) * 128 + arow] = av1.z;
        sA[(akoff + 7) * 128 + arow] = av1.w;
        *(float4*)&sB[bk * 128 + bn]      = bv0;
        *(float4*)&sB[bk * 128 + 64 + bn] = bv1;
        __syncthreads();

#pragma unroll
        for (int kk = 0; kk < 16; kk++) {
            float4 a0 = *(const float4*)&sA[kk * 128 + ty * 4];
            float4 a1 = *(const float4*)&sA[kk * 128 + 64 + ty * 4];
            float4 b0 = *(const float4*)&sB[kk * 128 + tx * 4];
            float4 b1 = *(const float4*)&sB[kk * 128 + 64 + tx * 4];
            ull bp[4];
            bp[0] = ((const ull*)&b0)[0];   // cols tx*4+0,1
            bp[1] = ((const ull*)&b0)[1];   // cols tx*4+2,3
            bp[2] = ((const ull*)&b1)[0];   // cols 64+tx*4+0,1
            bp[3] = ((const ull*)&b1)[1];   // cols 64+tx*4+2,3
            float ar[8] = {a0.x, a0.y, a0.z, a0.w, a1.x, a1.y, a1.z, a1.w};
#pragma unroll
            for (int r = 0; r < 8; r++) {
                ull as = splat2(ar[r]);
#pragma unroll
                for (int c = 0; c < 4; c++)
                    acc[r][c] = fma2(as, bp[c], acc[r][c]);
            }
        }
    }

    float4 bias0 = ((const float4*)bias)[tx];
    float4 bias1 = ((const float4*)bias)[16 + tx];
    float4* out4 = (float4*)out;
#pragma unroll
    for (int r = 0; r < 8; r++) {
        int row = blockRow + ((r < 4) ? (ty * 4 + r) : (64 + ty * 4 + (r - 4)));
        if (row >= n) continue;
        float2 p0 = *(float2*)&acc[r][0];
        float2 p1 = *(float2*)&acc[r][1];
        float2 p2 = *(float2*)&acc[r][2];
        float2 p3 = *(float2*)&acc[r][3];
        float4 o0, o1;
        o0.x = fmaxf(p0.x + bias0.x, 0.f);
        o0.y = fmaxf(p0.y + bias0.y, 0.f);
        o0.z = fmaxf(p1.x + bias0.z, 0.f);
        o0.w = fmaxf(p1.y + bias0.w, 0.f);
        o1.x = fmaxf(p2.x + bias1.x, 0.f);
        o1.y = fmaxf(p2.y + bias1.y, 0.f);
        o1.z = fmaxf(p3.x + bias1.z, 0.f);
        o1.w = fmaxf(p3.y + bias1.w, 0.f);
        out4[(size_t)row * 32 + tx]      = o0;
        out4[(size_t)row * 32 + 16 + tx] = o1;
    }
}

// ---------------- launch ----------------
extern "C" void kernel_launch(void* const* d_in, const int* in_sizes, int n_in,
                              void* d_out, int out_size) {
    const float* x    = (const float*)d_in[0];
    const float* Ws   = (const float*)d_in[1];
    const float* Wn   = (const float*)d_in[2];
    const float* bias = (const float*)d_in[3];
    const int*   src  = (const int*)d_in[4];
    const int*   dst  = (const int*)d_in[5];
    int n = in_sizes[0] / D;
    int e = in_sizes[4];
    float* out = (float*)d_out;

    k_zero_deg<<<(n + 255) / 256, 256>>>(n);
    k_count<<<(e + 255) / 256, 256>>>(dst, e);
    k_scan<<<1, 1024>>>(n);
    k_fill<<<(e + 255) / 256, 256>>>(src, dst, e);

    for (int l = 0; l < 3; l++) {
        k_agg<<<(n * 32 + 255) / 256, 256>>>(x, l, n);
        k_gemm<<<(n + 127) / 128, 256>>>(x, out, Ws + l * D * D, Wn + l * D * D,
                                         bias + l * D, l, n);
    }
}